// round 13
// baseline (speedup 1.0000x reference)
#include <cuda_runtime.h>
#include <cuda_bf16.h>
#include <math.h>
#include <stdint.h>

#define BN 4
#define HH 128
#define WW 128
#define HWS (HH * WW)
#define CC 64
#define O1 64
#define O2 32
#define NOFF 27
#define NPIX (BN * HWS)
#define TP 128
#define ST 72              // smem row stride in bf16 elems (144B)

#define SM_AH   0
#define SM_AL   18432
#define SM_BH   36864      // B hi; sized NMAIN*144; B lo follows

// ---------------- device scratch ----------------
__device__ float g_x2[BN * CC * HWS];
__device__ __align__(16) __nv_bfloat16 g_w1h[9 * O1 * CC];
__device__ __align__(16) __nv_bfloat16 g_w1l[9 * O1 * CC];
__device__ __align__(16) __nv_bfloat16 g_w2h[9 * O2 * CC];
__device__ __align__(16) __nv_bfloat16 g_w2l[9 * O2 * CC];
__device__ __align__(16) __nv_bfloat16 g_o1h[9 * O2 * CC];
__device__ __align__(16) __nv_bfloat16 g_o1l[9 * O2 * CC];
__device__ __align__(16) __nv_bfloat16 g_o2h[9 * O2 * CC];
__device__ __align__(16) __nv_bfloat16 g_o2l[9 * O2 * CC];
__device__ float g_b1[O1];
__device__ float g_b2[O2];

// ---------------- helpers ----------------
__device__ __forceinline__ unsigned smem_u32(const void* p) {
    unsigned a;
    asm("{ .reg .u64 t; cvta.to.shared.u64 t, %1; cvt.u32.u64 %0, t; }" : "=r"(a) : "l"(p));
    return a;
}
__device__ __forceinline__ void ldsm4(unsigned* r, unsigned addr) {
    asm volatile("ldmatrix.sync.aligned.m8n8.x4.shared.b16 {%0,%1,%2,%3}, [%4];"
                 : "=r"(r[0]), "=r"(r[1]), "=r"(r[2]), "=r"(r[3]) : "r"(addr));
}
__device__ __forceinline__ void mma16816(float* c, const unsigned* a, unsigned b0, unsigned b1) {
    asm volatile(
        "mma.sync.aligned.m16n8k16.row.col.f32.bf16.bf16.f32 "
        "{%0,%1,%2,%3}, {%4,%5,%6,%7}, {%8,%9}, {%0,%1,%2,%3};"
        : "+f"(c[0]), "+f"(c[1]), "+f"(c[2]), "+f"(c[3])
        : "r"(a[0]), "r"(a[1]), "r"(a[2]), "r"(a[3]), "r"(b0), "r"(b1));
}
__device__ __forceinline__ unsigned bf16x2_rn(float lo, float hi) {
    unsigned r;
    asm("cvt.rn.bf16x2.f32 %0, %1, %2;" : "=r"(r) : "f"(hi), "f"(lo));
    return r;
}
__device__ __forceinline__ void cvt_hilo(float v0, float v1, unsigned& hw, unsigned& lw) {
    hw = bf16x2_rn(v0, v1);
    float h0 = __uint_as_float(hw << 16);
    float h1 = __uint_as_float(hw & 0xFFFF0000u);
    lw = bf16x2_rn(v0 - h0, v1 - h1);
}
__device__ __forceinline__ void cp_async16(unsigned dst, const void* src) {
    asm volatile("cp.async.cg.shared.global [%0], [%1], 16;" :: "r"(dst), "l"(src) : "memory");
}
__device__ __forceinline__ void cp_commit() {
    asm volatile("cp.async.commit_group;" ::: "memory");
}
__device__ __forceinline__ void cp_wait0() {
    asm volatile("cp.async.wait_group 0;" ::: "memory");
}

// ---------------- prep (weights only) ----------------
__global__ void prep_kernel(
    const float* __restrict__ wo1,
    const float* __restrict__ w1, const float* __restrict__ g1,
    const float* __restrict__ be1, const float* __restrict__ rm1, const float* __restrict__ rv1,
    const float* __restrict__ wo2,
    const float* __restrict__ w2, const float* __restrict__ g2,
    const float* __restrict__ be2, const float* __restrict__ rm2, const float* __restrict__ rv2)
{
    int t = blockIdx.x * blockDim.x + threadIdx.x;
    int stride = gridDim.x * blockDim.x;

    for (int i = t; i < 9 * O1 * CC; i += stride) {
        int c = i & 63;
        int o = (i >> 6) & 63;
        int k = i >> 12;
        float inv = g1[o] * rsqrtf(rv1[o] + 1e-5f);
        float v = w1[(o * CC + c) * 9 + k] * inv;
        __nv_bfloat16 hb = __float2bfloat16(v);
        g_w1h[i] = hb;
        g_w1l[i] = __float2bfloat16(v - __bfloat162float(hb));
    }
    for (int i = t; i < 9 * O2 * CC; i += stride) {
        int c = i & 63;
        int o = (i >> 6) & 31;
        int k = i >> 11;
        float inv = g2[o] * rsqrtf(rv2[o] + 1e-5f);
        float v = w2[(o * CC + c) * 9 + k] * inv;
        __nv_bfloat16 hb = __float2bfloat16(v);
        g_w2h[i] = hb;
        g_w2l[i] = __float2bfloat16(v - __bfloat162float(hb));
    }
    for (int i = t; i < 9 * O2 * CC; i += stride) {
        int c = i & 63;
        int o = (i >> 6) & 31;
        int k = i >> 11;
        float v1 = (o < NOFF) ? wo1[(o * CC + c) * 9 + k] : 0.f;
        float v2 = (o < NOFF) ? wo2[(o * CC + c) * 9 + k] : 0.f;
        __nv_bfloat16 h1 = __float2bfloat16(v1);
        __nv_bfloat16 h2 = __float2bfloat16(v2);
        g_o1h[i] = h1; g_o1l[i] = __float2bfloat16(v1 - __bfloat162float(h1));
        g_o2h[i] = h2; g_o2l[i] = __float2bfloat16(v2 - __bfloat162float(h2));
    }
    if (t < O1) { float inv = g1[t] * rsqrtf(rv1[t] + 1e-5f); g_b1[t] = be1[t] - rm1[t] * inv; }
    if (t < O2) { float inv = g2[t] * rsqrtf(rv2[t] + 1e-5f); g_b2[t] = be2[t] - rm2[t] * inv; }
}

// ---------------- gather one tap into registers ----------------
template <int MODE>
__device__ __forceinline__ void gather_tap(
    const float* __restrict__ xc,      // channel-half base [32][HWS]
    const float* __restrict__ soff,
    int h, int p, int k,
    unsigned* hw, unsigned* lw)
{
    if (MODE == 0) {
        int gy = h + k / 3 - 1;
        int gx = p + k % 3 - 1;
        bool ok = (gy >= 0 && gy < HH && gx >= 0 && gx < WW);
        const float* src = xc + gy * WW + gx;
#pragma unroll
        for (int j = 0; j < 16; j++) {
            float v0 = ok ? __ldg(src + (2 * j) * HWS) : 0.f;
            float v1 = ok ? __ldg(src + (2 * j + 1) * HWS) : 0.f;
            cvt_hilo(v0, v1, hw[j], lw[j]);
        }
    } else {
        float dy = soff[(2 * k) * TP + p];
        float dx = soff[(2 * k + 1) * TP + p];
        float m  = soff[(18 + k) * TP + p];      // pre-sigmoided

        float ys = (float)(h + (k / 3 - 1)) + dy;
        float xs = (float)(p + (k % 3 - 1)) + dx;
        float y0f = floorf(ys), x0f = floorf(xs);
        float fy = ys - y0f, fx = xs - x0f;
        int y0 = (int)y0f, x0 = (int)x0f;
        int y1 = y0 + 1, x1 = x0 + 1;

        float vy0 = (y0 >= 0 && y0 < HH) ? m : 0.f;
        float vy1 = (y1 >= 0 && y1 < HH) ? m : 0.f;
        float vx0 = (x0 >= 0 && x0 < WW) ? 1.f : 0.f;
        float vx1 = (x1 >= 0 && x1 < WW) ? 1.f : 0.f;

        float w00 = (1.f - fy) * (1.f - fx) * vy0 * vx0;
        float w01 = (1.f - fy) * fx * vy0 * vx1;
        float w10 = fy * (1.f - fx) * vy1 * vx0;
        float w11 = fy * fx * vy1 * vx1;

        int cy0 = min(max(y0, 0), HH - 1), cy1 = min(max(y1, 0), HH - 1);
        int cx0 = min(max(x0, 0), WW - 1), cx1 = min(max(x1, 0), WW - 1);
        int i00 = cy0 * WW + cx0, i01 = cy0 * WW + cx1;
        int i10 = cy1 * WW + cx0, i11 = cy1 * WW + cx1;

#pragma unroll
        for (int j = 0; j < 16; j++) {
            const float* x0p = xc + (2 * j) * HWS;
            const float* x1p = x0p + HWS;
            float v0 = w00 * __ldg(x0p + i00) + w01 * __ldg(x0p + i01)
                     + w10 * __ldg(x0p + i10) + w11 * __ldg(x0p + i11);
            float v1 = w00 * __ldg(x1p + i00) + w01 * __ldg(x1p + i01)
                     + w10 * __ldg(x1p + i10) + w11 * __ldg(x1p + i11);
            cvt_hilo(v0, v1, hw[j], lw[j]);
        }
    }
}

__device__ __forceinline__ void store_tap(char* sm, int p, int cb,
                                          const unsigned* hw, const unsigned* lw)
{
#pragma unroll
    for (int j = 0; j < 8; j++) {
        unsigned boff = (unsigned)(p * ST + cb + 4 * j) * 2u;
        *(uint2*)(sm + SM_AH + boff) = make_uint2(hw[2 * j], hw[2 * j + 1]);
        *(uint2*)(sm + SM_AL + boff) = make_uint2(lw[2 * j], lw[2 * j + 1]);
    }
}

// issue cp.async for B chunk of tap k (no wait)
template <int N>
__device__ __forceinline__ void stage_B_cp(unsigned sb, int tid, int k,
                                           const __nv_bfloat16* __restrict__ wh,
                                           const __nv_bfloat16* __restrict__ wl)
{
    constexpr unsigned BL = SM_BH + (unsigned)N * 144u;
    const uint4* shp = (const uint4*)(wh + k * (N * CC));
    const uint4* slp = (const uint4*)(wl + k * (N * CC));
#pragma unroll
    for (int t2 = 0; t2 < (N * 8) / 256; t2++) {
        int i = tid + t2 * 256;
        int n = i >> 3, j = i & 7;
        unsigned d = (unsigned)(n * 144 + j * 16);
        cp_async16(sb + SM_BH + d, shp + i);
        cp_async16(sb + BL + d, slp + i);
    }
    cp_commit();
}

// ---------------- pipelined conv phase (9 taps, bf16x3 MMA) ----------------
// BCP: stage B via cp.async (frees registers); else register prefetch.
template <int N, int MODE, bool BCP>
__device__ __forceinline__ void run_conv(
    char* sm, unsigned sb,
    const float* __restrict__ xc, const float* __restrict__ soff,
    const __nv_bfloat16* __restrict__ wh, const __nv_bfloat16* __restrict__ wl,
    int h, int p, int cb, int tid, int wid, int lid,
    float (&acc)[N / 8][4])
{
    constexpr int NF16 = N / 16;
    constexpr int NBI  = (N * 32) / 256;
    constexpr unsigned BL = SM_BH + (unsigned)N * 144u;

    const int lrow = lid & 15;
    const int lkof = (lid >> 4) * 8;
    const unsigned a_base = sb + ((wid * 16 + lrow) * ST + lkof) * 2;

    unsigned hw[16], lw[16];
    unsigned rbh[BCP ? 1 : NBI], rbl[BCP ? 1 : NBI];

    // ---- prologue: stage tap 0 ----
    gather_tap<MODE>(xc, soff, h, p, 0, hw, lw);
    if (BCP) {
        stage_B_cp<N>(sb, tid, 0, wh, wl);
        store_tap(sm, p, cb, hw, lw);
        cp_wait0();
    } else {
        const unsigned* shp = (const unsigned*)wh;
        const unsigned* slp = (const unsigned*)wl;
#pragma unroll
        for (int t2 = 0; t2 < NBI; t2++) {
            rbh[t2] = __ldg(shp + tid + t2 * 256);
            rbl[t2] = __ldg(slp + tid + t2 * 256);
        }
        store_tap(sm, p, cb, hw, lw);
#pragma unroll
        for (int t2 = 0; t2 < NBI; t2++) {
            int i = tid + t2 * 256;
            int n = i >> 5, kw = i & 31;
            ((unsigned*)(sm + SM_BH))[n * (ST / 2) + kw] = rbh[t2];
            ((unsigned*)(sm + BL))[n * (ST / 2) + kw] = rbl[t2];
        }
    }
    __syncthreads();

#pragma unroll 1
    for (int k = 0; k < 9; k++) {
        if (k < 8) {
            gather_tap<MODE>(xc, soff, h, p, k + 1, hw, lw);
            if (!BCP) {
                const unsigned* shp = (const unsigned*)(wh + (k + 1) * (N * CC));
                const unsigned* slp = (const unsigned*)(wl + (k + 1) * (N * CC));
#pragma unroll
                for (int t2 = 0; t2 < NBI; t2++) {
                    rbh[t2] = __ldg(shp + tid + t2 * 256);
                    rbl[t2] = __ldg(slp + tid + t2 * 256);
                }
            }
        }

#pragma unroll
        for (int q = 0; q < 4; q++) {
            unsigned ah[4], al[4];
            ldsm4(ah, a_base + SM_AH + q * 32);
            ldsm4(al, a_base + SM_AL + q * 32);
#pragma unroll
            for (int nf = 0; nf < NF16; nf++) {
                unsigned bh[4], bl[4];
                unsigned b_base = sb + ((nf * 16 + lrow) * ST + q * 16 + lkof) * 2;
                ldsm4(bh, b_base + SM_BH);
                ldsm4(bl, b_base + BL);
                mma16816(acc[nf * 2],     ah, bh[0], bh[2]);
                mma16816(acc[nf * 2 + 1], ah, bh[1], bh[3]);
                mma16816(acc[nf * 2],     ah, bl[0], bl[2]);
                mma16816(acc[nf * 2 + 1], ah, bl[1], bl[3]);
                mma16816(acc[nf * 2],     al, bh[0], bh[2]);
                mma16816(acc[nf * 2 + 1], al, bh[1], bh[3]);
            }
        }
        __syncthreads();

        if (k < 8) {
            if (BCP) {
                stage_B_cp<N>(sb, tid, k + 1, wh, wl);
                store_tap(sm, p, cb, hw, lw);
                cp_wait0();
            } else {
                store_tap(sm, p, cb, hw, lw);
#pragma unroll
                for (int t2 = 0; t2 < NBI; t2++) {
                    int i = tid + t2 * 256;
                    int n = i >> 5, kw = i & 31;
                    ((unsigned*)(sm + SM_BH))[n * (ST / 2) + kw] = rbh[t2];
                    ((unsigned*)(sm + BL))[n * (ST / 2) + kw] = rbl[t2];
                }
            }
            __syncthreads();
        }
    }
}

// ---------------- fused layer: offconv -> smem offsets -> deform conv ----------------
template <int NMAIN, int MODE2, int MINB, bool BCP>
__global__ __launch_bounds__(256, MINB)
void fused_layer_kernel(const float* __restrict__ xA, const float* __restrict__ xB,
                        long bstr,
                        const __nv_bfloat16* __restrict__ owh, const __nv_bfloat16* __restrict__ owl,
                        const float* __restrict__ obias,
                        const __nv_bfloat16* __restrict__ mwh, const __nv_bfloat16* __restrict__ mwl,
                        const float* __restrict__ mbias,
                        float* __restrict__ out,
                        const float* __restrict__ Aatt, const float* __restrict__ Batt)
{
    extern __shared__ __align__(16) char sm[];
    const unsigned sb = smem_u32(sm);

    constexpr unsigned SM_OFF = SM_BH + 2u * (unsigned)NMAIN * 144u;
    float* soff = (float*)(sm + SM_OFF);            // [27][128]

    const int tid = threadIdx.x;
    const int wid = tid >> 5;
    const int lid = tid & 31;

    const int b  = blockIdx.x >> 7;
    const int h  = blockIdx.x & 127;
    const int sl = h * WW;

    const int p  = tid & 127;
    const int cb = (tid >> 7) * 32;
    const float* xc = ((tid >> 7) == 0) ? (xA + b * bstr) : (xB + b * bstr);

    const int gm = lid >> 2;
    const int gn = (lid & 3) * 2;
    const int px0 = wid * 16 + gm;
    const int px1 = px0 + 8;

    // ===== phase 1: offset conv (N=32) =====
    {
        float acc[4][4];
#pragma unroll
        for (int i = 0; i < 4; i++)
#pragma unroll
            for (int j = 0; j < 4; j++) acc[i][j] = 0.f;

        run_conv<32, 0, BCP>(sm, sb, xc, nullptr, owh, owl,
                             h, p, cb, tid, wid, lid, acc);

#pragma unroll
        for (int nf = 0; nf < 4; nf++) {
            int o = nf * 8 + gn;
#pragma unroll
            for (int e = 0; e < 2; e++) {
                int oo = o + e;
                if (oo < NOFF) {
                    float bb = __ldg(obias + oo);
                    float v0 = acc[nf][e] + bb;
                    float v1 = acc[nf][e + 2] + bb;
                    if (oo >= 18) {
                        v0 = 1.f / (1.f + expf(-v0));
                        v1 = 1.f / (1.f + expf(-v1));
                    }
                    soff[oo * TP + px0] = v0;
                    soff[oo * TP + px1] = v1;
                }
            }
        }
        __syncthreads();
    }

    // ===== phase 2: deform conv (N = NMAIN) =====
    {
        float acc[NMAIN / 8][4];
#pragma unroll
        for (int i = 0; i < NMAIN / 8; i++)
#pragma unroll
            for (int j = 0; j < 4; j++) acc[i][j] = 0.f;

        run_conv<NMAIN, 1, BCP>(sm, sb, xc, soff, mwh, mwl,
                                h, p, cb, tid, wid, lid, acc);

        const int g0 = sl + px0;
        const int g1i = sl + px1;

        float ga0 = 1.f, ga1 = 1.f;
        if (MODE2 == 2) {
            ga0 = (1.f - __ldg(Aatt + b * HWS + g0)) * __ldg(Batt + b * HWS + g0);
            ga1 = (1.f - __ldg(Aatt + b * HWS + g1i)) * __ldg(Batt + b * HWS + g1i);
        }

#pragma unroll
        for (int nf = 0; nf < NMAIN / 8; nf++) {
            int o = nf * 8 + gn;
#pragma unroll
            for (int e = 0; e < 2; e++) {
                int oo = o + e;
                float bb = __ldg(mbias + oo);
                float v0 = fmaxf(acc[nf][e] + bb, 0.f);
                float v1 = fmaxf(acc[nf][e + 2] + bb, 0.f);
                if (MODE2 == 2) { v0 *= ga0; v1 *= ga1; }
                out[(b * NMAIN + oo) * HWS + g0]  = v0;
                out[(b * NMAIN + oo) * HWS + g1i] = v1;
            }
        }
    }
}

// ---------------- launch ----------------
extern "C" void kernel_launch(void* const* d_in, const int* in_sizes, int n_in,
                              void* d_out, int out_size)
{
    const float* pA   = (const float*)d_in[1];
    const float* pB   = (const float*)d_in[2];
    const float* Aatt = (const float*)d_in[3];
    const float* Batt = (const float*)d_in[4];
    const float* wo1  = (const float*)d_in[5];
    const float* bo1  = (const float*)d_in[6];
    const float* w1   = (const float*)d_in[7];
    const float* g1   = (const float*)d_in[8];
    const float* be1  = (const float*)d_in[9];
    const float* rm1  = (const float*)d_in[10];
    const float* rv1  = (const float*)d_in[11];
    const float* wo2  = (const float*)d_in[12];
    const float* bo2  = (const float*)d_in[13];
    const float* w2   = (const float*)d_in[14];
    const float* g2   = (const float*)d_in[15];
    const float* be2  = (const float*)d_in[16];
    const float* rm2  = (const float*)d_in[17];
    const float* rv2  = (const float*)d_in[18];

    float *x2, *pb1, *pb2;
    __nv_bfloat16 *w1h, *w1l, *w2h, *w2l, *o1h, *o1l, *o2h, *o2l;
    cudaGetSymbolAddress((void**)&x2,  g_x2);
    cudaGetSymbolAddress((void**)&pb1, g_b1);
    cudaGetSymbolAddress((void**)&pb2, g_b2);
    cudaGetSymbolAddress((void**)&w1h, g_w1h);
    cudaGetSymbolAddress((void**)&w1l, g_w1l);
    cudaGetSymbolAddress((void**)&w2h, g_w2h);
    cudaGetSymbolAddress((void**)&w2l, g_w2l);
    cudaGetSymbolAddress((void**)&o1h, g_o1h);
    cudaGetSymbolAddress((void**)&o1l, g_o1l);
    cudaGetSymbolAddress((void**)&o2h, g_o2h);
    cudaGetSymbolAddress((void**)&o2l, g_o2l);

    const int smem1 = SM_BH + 2 * (O1 * 144) + NOFF * TP * 4;   // 69120
    const int smem2 = SM_BH + 2 * (O2 * 144) + NOFF * TP * 4;   // 59904
    cudaFuncSetAttribute(fused_layer_kernel<O1, 1, 3, true>, cudaFuncAttributeMaxDynamicSharedMemorySize, smem1);
    cudaFuncSetAttribute(fused_layer_kernel<O2, 2, 3, false>, cudaFuncAttributeMaxDynamicSharedMemorySize, smem2);

    dim3 blk(256);
    dim3 grd(NPIX / TP);   // 512

    prep_kernel<<<256, 256>>>(wo1, w1, g1, be1, rm1, rv1,
                              wo2, w2, g2, be2, rm2, rv2);

    fused_layer_kernel<O1, 1, 3, true><<<grd, blk, smem1>>>(
        pB, pA, 32L * HWS, o1h, o1l, bo1, w1h, w1l, pb1, x2, nullptr, nullptr);
    fused_layer_kernel<O2, 2, 3, false><<<grd, blk, smem2>>>(
        x2, x2 + 32 * HWS, 64L * HWS, o2h, o2l, bo2, w2h, w2l, pb2,
        (float*)d_out, Aatt, Batt);
}

// round 14
// speedup vs baseline: 1.1523x; 1.1523x over previous
#include <cuda_runtime.h>
#include <cuda_bf16.h>
#include <math.h>
#include <stdint.h>

#define BN 4
#define HH 128
#define WW 128
#define HWS (HH * WW)
#define CC 64
#define O1 64
#define O2 32
#define NOFF 27
#define NPIX (BN * HWS)
#define TP 128
#define ST 72              // smem row stride in bf16 elems (144B)

#define SM_AH   0
#define SM_AL   18432
#define SM_BH   36864      // B hi; sized NMAIN*144; B lo follows

// ---------------- device scratch ----------------
__device__ float g_x2[BN * CC * HWS];
__device__ __align__(16) __nv_bfloat16 g_w1h[9 * O1 * CC];
__device__ __align__(16) __nv_bfloat16 g_w1l[9 * O1 * CC];
__device__ __align__(16) __nv_bfloat16 g_w2h[9 * O2 * CC];
__device__ __align__(16) __nv_bfloat16 g_w2l[9 * O2 * CC];
__device__ __align__(16) __nv_bfloat16 g_o1h[9 * O2 * CC];
__device__ __align__(16) __nv_bfloat16 g_o1l[9 * O2 * CC];
__device__ __align__(16) __nv_bfloat16 g_o2h[9 * O2 * CC];
__device__ __align__(16) __nv_bfloat16 g_o2l[9 * O2 * CC];
__device__ float g_b1[O1];
__device__ float g_b2[O2];

// ---------------- helpers ----------------
__device__ __forceinline__ unsigned smem_u32(const void* p) {
    unsigned a;
    asm("{ .reg .u64 t; cvta.to.shared.u64 t, %1; cvt.u32.u64 %0, t; }" : "=r"(a) : "l"(p));
    return a;
}
__device__ __forceinline__ void ldsm4(unsigned* r, unsigned addr) {
    asm volatile("ldmatrix.sync.aligned.m8n8.x4.shared.b16 {%0,%1,%2,%3}, [%4];"
                 : "=r"(r[0]), "=r"(r[1]), "=r"(r[2]), "=r"(r[3]) : "r"(addr));
}
__device__ __forceinline__ void mma16816(float* c, const unsigned* a, unsigned b0, unsigned b1) {
    asm volatile(
        "mma.sync.aligned.m16n8k16.row.col.f32.bf16.bf16.f32 "
        "{%0,%1,%2,%3}, {%4,%5,%6,%7}, {%8,%9}, {%0,%1,%2,%3};"
        : "+f"(c[0]), "+f"(c[1]), "+f"(c[2]), "+f"(c[3])
        : "r"(a[0]), "r"(a[1]), "r"(a[2]), "r"(a[3]), "r"(b0), "r"(b1));
}
__device__ __forceinline__ unsigned bf16x2_rn(float lo, float hi) {
    unsigned r;
    asm("cvt.rn.bf16x2.f32 %0, %1, %2;" : "=r"(r) : "f"(hi), "f"(lo));
    return r;
}
__device__ __forceinline__ void cvt_hilo(float v0, float v1, unsigned& hw, unsigned& lw) {
    hw = bf16x2_rn(v0, v1);
    float h0 = __uint_as_float(hw << 16);
    float h1 = __uint_as_float(hw & 0xFFFF0000u);
    lw = bf16x2_rn(v0 - h0, v1 - h1);
}
__device__ __forceinline__ float fast_sigmoid(float x) {
    return __fdividef(1.f, 1.f + __expf(-x));
}

// ---------------- prep (weights only) ----------------
__global__ void prep_kernel(
    const float* __restrict__ wo1,
    const float* __restrict__ w1, const float* __restrict__ g1,
    const float* __restrict__ be1, const float* __restrict__ rm1, const float* __restrict__ rv1,
    const float* __restrict__ wo2,
    const float* __restrict__ w2, const float* __restrict__ g2,
    const float* __restrict__ be2, const float* __restrict__ rm2, const float* __restrict__ rv2)
{
    int t = blockIdx.x * blockDim.x + threadIdx.x;
    int stride = gridDim.x * blockDim.x;

    for (int i = t; i < 9 * O1 * CC; i += stride) {
        int c = i & 63;
        int o = (i >> 6) & 63;
        int k = i >> 12;
        float inv = g1[o] * rsqrtf(rv1[o] + 1e-5f);
        float v = w1[(o * CC + c) * 9 + k] * inv;
        __nv_bfloat16 hb = __float2bfloat16(v);
        g_w1h[i] = hb;
        g_w1l[i] = __float2bfloat16(v - __bfloat162float(hb));
    }
    for (int i = t; i < 9 * O2 * CC; i += stride) {
        int c = i & 63;
        int o = (i >> 6) & 31;
        int k = i >> 11;
        float inv = g2[o] * rsqrtf(rv2[o] + 1e-5f);
        float v = w2[(o * CC + c) * 9 + k] * inv;
        __nv_bfloat16 hb = __float2bfloat16(v);
        g_w2h[i] = hb;
        g_w2l[i] = __float2bfloat16(v - __bfloat162float(hb));
    }
    for (int i = t; i < 9 * O2 * CC; i += stride) {
        int c = i & 63;
        int o = (i >> 6) & 31;
        int k = i >> 11;
        float v1 = (o < NOFF) ? wo1[(o * CC + c) * 9 + k] : 0.f;
        float v2 = (o < NOFF) ? wo2[(o * CC + c) * 9 + k] : 0.f;
        __nv_bfloat16 h1 = __float2bfloat16(v1);
        __nv_bfloat16 h2 = __float2bfloat16(v2);
        g_o1h[i] = h1; g_o1l[i] = __float2bfloat16(v1 - __bfloat162float(h1));
        g_o2h[i] = h2; g_o2l[i] = __float2bfloat16(v2 - __bfloat162float(h2));
    }
    if (t < O1) { float inv = g1[t] * rsqrtf(rv1[t] + 1e-5f); g_b1[t] = be1[t] - rm1[t] * inv; }
    if (t < O2) { float inv = g2[t] * rsqrtf(rv2[t] + 1e-5f); g_b2[t] = be2[t] - rm2[t] * inv; }
}

// ---------------- gather one tap into registers ----------------
// MODE 0: integer tap. MODE 1: bilinear tap, offsets from smem soff[o][TP].
template <int MODE>
__device__ __forceinline__ void gather_tap(
    const float* __restrict__ xc,      // channel-half base [32][HWS]
    const float* __restrict__ soff,
    int h, int p, int k,
    unsigned* hw, unsigned* lw)
{
    if (MODE == 0) {
        int gy = h + k / 3 - 1;
        int gx = p + k % 3 - 1;
        bool ok = (gy >= 0 && gy < HH && gx >= 0 && gx < WW);
        const float* src = xc + gy * WW + gx;
#pragma unroll
        for (int j = 0; j < 16; j++) {
            float v0 = ok ? __ldg(src + (2 * j) * HWS) : 0.f;
            float v1 = ok ? __ldg(src + (2 * j + 1) * HWS) : 0.f;
            cvt_hilo(v0, v1, hw[j], lw[j]);
        }
    } else {
        float dy = soff[(2 * k) * TP + p];
        float dx = soff[(2 * k + 1) * TP + p];
        float m  = soff[(18 + k) * TP + p];      // pre-sigmoided

        float ys = (float)(h + (k / 3 - 1)) + dy;
        float xs = (float)(p + (k % 3 - 1)) + dx;
        float y0f = floorf(ys), x0f = floorf(xs);
        float fy = ys - y0f, fx = xs - x0f;
        int y0 = (int)y0f, x0 = (int)x0f;
        int y1 = y0 + 1, x1 = x0 + 1;

        float vy0 = (y0 >= 0 && y0 < HH) ? m : 0.f;
        float vy1 = (y1 >= 0 && y1 < HH) ? m : 0.f;
        float vx0 = (x0 >= 0 && x0 < WW) ? 1.f : 0.f;
        float vx1 = (x1 >= 0 && x1 < WW) ? 1.f : 0.f;

        float w00 = (1.f - fy) * (1.f - fx) * vy0 * vx0;
        float w01 = (1.f - fy) * fx * vy0 * vx1;
        float w10 = fy * (1.f - fx) * vy1 * vx0;
        float w11 = fy * fx * vy1 * vx1;

        int cy0 = min(max(y0, 0), HH - 1), cy1 = min(max(y1, 0), HH - 1);
        int cx0 = min(max(x0, 0), WW - 1), cx1 = min(max(x1, 0), WW - 1);
        int i00 = cy0 * WW + cx0, i01 = cy0 * WW + cx1;
        int i10 = cy1 * WW + cx0, i11 = cy1 * WW + cx1;

#pragma unroll
        for (int j = 0; j < 16; j++) {
            const float* x0p = xc + (2 * j) * HWS;
            const float* x1p = x0p + HWS;
            float v0 = w00 * __ldg(x0p + i00) + w01 * __ldg(x0p + i01)
                     + w10 * __ldg(x0p + i10) + w11 * __ldg(x0p + i11);
            float v1 = w00 * __ldg(x1p + i00) + w01 * __ldg(x1p + i01)
                     + w10 * __ldg(x1p + i10) + w11 * __ldg(x1p + i11);
            cvt_hilo(v0, v1, hw[j], lw[j]);
        }
    }
}

__device__ __forceinline__ void store_tap(char* sm, int p, int cb,
                                          const unsigned* hw, const unsigned* lw)
{
#pragma unroll
    for (int j = 0; j < 8; j++) {
        unsigned boff = (unsigned)(p * ST + cb + 4 * j) * 2u;
        *(uint2*)(sm + SM_AH + boff) = make_uint2(hw[2 * j], hw[2 * j + 1]);
        *(uint2*)(sm + SM_AL + boff) = make_uint2(lw[2 * j], lw[2 * j + 1]);
    }
}

// ---------------- pipelined conv phase (9 taps, bf16x3 MMA) ----------------
template <int N, int MODE>
__device__ __forceinline__ void run_conv(
    char* sm, unsigned sb,
    const float* __restrict__ xc, const float* __restrict__ soff,
    const __nv_bfloat16* __restrict__ wh, const __nv_bfloat16* __restrict__ wl,
    int h, int p, int cb, int tid, int wid, int lid,
    float (&acc)[N / 8][4])
{
    constexpr int NF16 = N / 16;
    constexpr int NBI  = (N * 32) / 256;
    constexpr unsigned BL = SM_BH + (unsigned)N * 144u;

    const int lrow = lid & 15;
    const int lkof = (lid >> 4) * 8;
    const unsigned a_base = sb + ((wid * 16 + lrow) * ST + lkof) * 2;

    unsigned hw[16], lw[16];
    unsigned rbh[NBI], rbl[NBI];

    // ---- prologue: stage tap 0 ----
    gather_tap<MODE>(xc, soff, h, p, 0, hw, lw);
    {
        const unsigned* shp = (const unsigned*)wh;
        const unsigned* slp = (const unsigned*)wl;
#pragma unroll
        for (int t2 = 0; t2 < NBI; t2++) {
            rbh[t2] = __ldg(shp + tid + t2 * 256);
            rbl[t2] = __ldg(slp + tid + t2 * 256);
        }
    }
    store_tap(sm, p, cb, hw, lw);
#pragma unroll
    for (int t2 = 0; t2 < NBI; t2++) {
        int i = tid + t2 * 256;
        int n = i >> 5, kw = i & 31;
        ((unsigned*)(sm + SM_BH))[n * (ST / 2) + kw] = rbh[t2];
        ((unsigned*)(sm + BL))[n * (ST / 2) + kw] = rbl[t2];
    }
    __syncthreads();

#pragma unroll 1
    for (int k = 0; k < 9; k++) {
        // ---- prefetch tap k+1 into registers ----
        if (k < 8) {
            gather_tap<MODE>(xc, soff, h, p, k + 1, hw, lw);
            const unsigned* shp = (const unsigned*)(wh + (k + 1) * (N * CC));
            const unsigned* slp = (const unsigned*)(wl + (k + 1) * (N * CC));
#pragma unroll
            for (int t2 = 0; t2 < NBI; t2++) {
                rbh[t2] = __ldg(shp + tid + t2 * 256);
                rbl[t2] = __ldg(slp + tid + t2 * 256);
            }
        }

        // ---- MMA tap k from smem ----
#pragma unroll
        for (int q = 0; q < 4; q++) {
            unsigned ah[4], al[4];
            ldsm4(ah, a_base + SM_AH + q * 32);
            ldsm4(al, a_base + SM_AL + q * 32);
#pragma unroll
            for (int nf = 0; nf < NF16; nf++) {
                unsigned bh[4], bl[4];
                unsigned b_base = sb + ((nf * 16 + lrow) * ST + q * 16 + lkof) * 2;
                ldsm4(bh, b_base + SM_BH);
                ldsm4(bl, b_base + BL);
                mma16816(acc[nf * 2],     ah, bh[0], bh[2]);
                mma16816(acc[nf * 2 + 1], ah, bh[1], bh[3]);
                mma16816(acc[nf * 2],     ah, bl[0], bl[2]);
                mma16816(acc[nf * 2 + 1], ah, bl[1], bl[3]);
                mma16816(acc[nf * 2],     al, bh[0], bh[2]);
                mma16816(acc[nf * 2 + 1], al, bh[1], bh[3]);
            }
        }
        __syncthreads();

        // ---- store tap k+1 ----
        if (k < 8) {
            store_tap(sm, p, cb, hw, lw);
#pragma unroll
            for (int t2 = 0; t2 < NBI; t2++) {
                int i = tid + t2 * 256;
                int n = i >> 5, kw = i & 31;
                ((unsigned*)(sm + SM_BH))[n * (ST / 2) + kw] = rbh[t2];
                ((unsigned*)(sm + BL))[n * (ST / 2) + kw] = rbl[t2];
            }
            __syncthreads();
        }
    }
}

// ---------------- fused layer: offconv -> smem offsets -> deform conv ----------------
// MODE2 1: bias+relu -> NCHW out. MODE2 2: bias+relu, gate -> out.
template <int NMAIN, int MODE2, int MINB>
__global__ __launch_bounds__(256, MINB)
void fused_layer_kernel(const float* __restrict__ xA, const float* __restrict__ xB,
                        long bstr,
                        const __nv_bfloat16* __restrict__ owh, const __nv_bfloat16* __restrict__ owl,
                        const float* __restrict__ obias,
                        const __nv_bfloat16* __restrict__ mwh, const __nv_bfloat16* __restrict__ mwl,
                        const float* __restrict__ mbias,
                        float* __restrict__ out,
                        const float* __restrict__ Aatt, const float* __restrict__ Batt)
{
    extern __shared__ __align__(16) char sm[];
    const unsigned sb = smem_u32(sm);

    constexpr unsigned SM_OFF = SM_BH + 2u * (unsigned)NMAIN * 144u;
    float* soff = (float*)(sm + SM_OFF);            // [27][128]

    const int tid = threadIdx.x;
    const int wid = tid >> 5;
    const int lid = tid & 31;

    const int b  = blockIdx.x >> 7;
    const int h  = blockIdx.x & 127;
    const int sl = h * WW;

    const int p  = tid & 127;
    const int cb = (tid >> 7) * 32;
    const float* xc = ((tid >> 7) == 0) ? (xA + b * bstr) : (xB + b * bstr);

    const int gm = lid >> 2;
    const int gn = (lid & 3) * 2;
    const int px0 = wid * 16 + gm;
    const int px1 = px0 + 8;

    // ===== phase 1: offset conv (N=32) =====
    {
        float acc[4][4];
#pragma unroll
        for (int i = 0; i < 4; i++)
#pragma unroll
            for (int j = 0; j < 4; j++) acc[i][j] = 0.f;

        run_conv<32, 0>(sm, sb, xc, nullptr, owh, owl,
                        h, p, cb, tid, wid, lid, acc);

#pragma unroll
        for (int nf = 0; nf < 4; nf++) {
            int o = nf * 8 + gn;
#pragma unroll
            for (int e = 0; e < 2; e++) {
                int oo = o + e;
                if (oo < NOFF) {
                    float bb = __ldg(obias + oo);
                    float v0 = acc[nf][e] + bb;
                    float v1 = acc[nf][e + 2] + bb;
                    if (oo >= 18) {
                        v0 = fast_sigmoid(v0);
                        v1 = fast_sigmoid(v1);
                    }
                    soff[oo * TP + px0] = v0;
                    soff[oo * TP + px1] = v1;
                }
            }
        }
        __syncthreads();
    }

    // ===== phase 2: deform conv (N = NMAIN) =====
    {
        float acc[NMAIN / 8][4];
#pragma unroll
        for (int i = 0; i < NMAIN / 8; i++)
#pragma unroll
            for (int j = 0; j < 4; j++) acc[i][j] = 0.f;

        run_conv<NMAIN, 1>(sm, sb, xc, soff, mwh, mwl,
                           h, p, cb, tid, wid, lid, acc);

        const int g0 = sl + px0;
        const int g1i = sl + px1;

        float ga0 = 1.f, ga1 = 1.f;
        if (MODE2 == 2) {
            ga0 = (1.f - __ldg(Aatt + b * HWS + g0)) * __ldg(Batt + b * HWS + g0);
            ga1 = (1.f - __ldg(Aatt + b * HWS + g1i)) * __ldg(Batt + b * HWS + g1i);
        }

#pragma unroll
        for (int nf = 0; nf < NMAIN / 8; nf++) {
            int o = nf * 8 + gn;
#pragma unroll
            for (int e = 0; e < 2; e++) {
                int oo = o + e;
                float bb = __ldg(mbias + oo);
                float v0 = fmaxf(acc[nf][e] + bb, 0.f);
                float v1 = fmaxf(acc[nf][e + 2] + bb, 0.f);
                if (MODE2 == 2) { v0 *= ga0; v1 *= ga1; }
                out[(b * NMAIN + oo) * HWS + g0]  = v0;
                out[(b * NMAIN + oo) * HWS + g1i] = v1;
            }
        }
    }
}

// ---------------- launch ----------------
extern "C" void kernel_launch(void* const* d_in, const int* in_sizes, int n_in,
                              void* d_out, int out_size)
{
    const float* pA   = (const float*)d_in[1];
    const float* pB   = (const float*)d_in[2];
    const float* Aatt = (const float*)d_in[3];
    const float* Batt = (const float*)d_in[4];
    const float* wo1  = (const float*)d_in[5];
    const float* bo1  = (const float*)d_in[6];
    const float* w1   = (const float*)d_in[7];
    const float* g1   = (const float*)d_in[8];
    const float* be1  = (const float*)d_in[9];
    const float* rm1  = (const float*)d_in[10];
    const float* rv1  = (const float*)d_in[11];
    const float* wo2  = (const float*)d_in[12];
    const float* bo2  = (const float*)d_in[13];
    const float* w2   = (const float*)d_in[14];
    const float* g2   = (const float*)d_in[15];
    const float* be2  = (const float*)d_in[16];
    const float* rm2  = (const float*)d_in[17];
    const float* rv2  = (const float*)d_in[18];

    float *x2, *pb1, *pb2;
    __nv_bfloat16 *w1h, *w1l, *w2h, *w2l, *o1h, *o1l, *o2h, *o2l;
    cudaGetSymbolAddress((void**)&x2,  g_x2);
    cudaGetSymbolAddress((void**)&pb1, g_b1);
    cudaGetSymbolAddress((void**)&pb2, g_b2);
    cudaGetSymbolAddress((void**)&w1h, g_w1h);
    cudaGetSymbolAddress((void**)&w1l, g_w1l);
    cudaGetSymbolAddress((void**)&w2h, g_w2h);
    cudaGetSymbolAddress((void**)&w2l, g_w2l);
    cudaGetSymbolAddress((void**)&o1h, g_o1h);
    cudaGetSymbolAddress((void**)&o1l, g_o1l);
    cudaGetSymbolAddress((void**)&o2h, g_o2h);
    cudaGetSymbolAddress((void**)&o2l, g_o2l);

    const int smem1 = SM_BH + 2 * (O1 * 144) + NOFF * TP * 4;   // 69120
    const int smem2 = SM_BH + 2 * (O2 * 144) + NOFF * TP * 4;   // 59904
    cudaFuncSetAttribute(fused_layer_kernel<O1, 1, 2>, cudaFuncAttributeMaxDynamicSharedMemorySize, smem1);
    cudaFuncSetAttribute(fused_layer_kernel<O2, 2, 3>, cudaFuncAttributeMaxDynamicSharedMemorySize, smem2);

    dim3 blk(256);
    dim3 grd(NPIX / TP);   // 512

    prep_kernel<<<64, 256>>>(wo1, w1, g1, be1, rm1, rv1,
                             wo2, w2, g2, be2, rm2, rv2);

    fused_layer_kernel<O1, 1, 2><<<grd, blk, smem1>>>(
        pB, pA, 32L * HWS, o1h, o1l, bo1, w1h, w1l, pb1, x2, nullptr, nullptr);
    fused_layer_kernel<O2, 2, 3><<<grd, blk, smem2>>>(
        x2, x2 + 32 * HWS, 64L * HWS, o2h, o2l, bo2, w2h, w2l, pb2,
        (float*)d_out, Aatt, Batt);
}

// round 15
// speedup vs baseline: 1.2264x; 1.0642x over previous
#include <cuda_runtime.h>
#include <cuda_bf16.h>
#include <math.h>
#include <stdint.h>

#define BN 4
#define HH 128
#define WW 128
#define HWS (HH * WW)
#define CC 64
#define O1 64
#define O2 32
#define NOFF 27
#define NPIX (BN * HWS)
#define TP 128
#define ST 72              // smem row stride in bf16 elems (144B)
#define STB 144

// smem byte offsets: A window 130 rows x 144B (hi/lo), then B hi/lo, then soff
#define SM_AH   0
#define SM_AL   18720      // 130*144
#define SM_BH   37440      // B hi; sized NMAIN*144; B lo follows

// ---------------- device scratch ----------------
__device__ float g_x2[BN * CC * HWS];
__device__ __align__(16) __nv_bfloat16 g_w1h[9 * O1 * CC];
__device__ __align__(16) __nv_bfloat16 g_w1l[9 * O1 * CC];
__device__ __align__(16) __nv_bfloat16 g_w2h[9 * O2 * CC];
__device__ __align__(16) __nv_bfloat16 g_w2l[9 * O2 * CC];
__device__ __align__(16) __nv_bfloat16 g_o1h[9 * O2 * CC];
__device__ __align__(16) __nv_bfloat16 g_o1l[9 * O2 * CC];
__device__ __align__(16) __nv_bfloat16 g_o2h[9 * O2 * CC];
__device__ __align__(16) __nv_bfloat16 g_o2l[9 * O2 * CC];
__device__ float g_b1[O1];
__device__ float g_b2[O2];

// ---------------- helpers ----------------
__device__ __forceinline__ unsigned smem_u32(const void* p) {
    unsigned a;
    asm("{ .reg .u64 t; cvta.to.shared.u64 t, %1; cvt.u32.u64 %0, t; }" : "=r"(a) : "l"(p));
    return a;
}
__device__ __forceinline__ void ldsm4(unsigned* r, unsigned addr) {
    asm volatile("ldmatrix.sync.aligned.m8n8.x4.shared.b16 {%0,%1,%2,%3}, [%4];"
                 : "=r"(r[0]), "=r"(r[1]), "=r"(r[2]), "=r"(r[3]) : "r"(addr));
}
__device__ __forceinline__ void mma16816(float* c, const unsigned* a, unsigned b0, unsigned b1) {
    asm volatile(
        "mma.sync.aligned.m16n8k16.row.col.f32.bf16.bf16.f32 "
        "{%0,%1,%2,%3}, {%4,%5,%6,%7}, {%8,%9}, {%0,%1,%2,%3};"
        : "+f"(c[0]), "+f"(c[1]), "+f"(c[2]), "+f"(c[3])
        : "r"(a[0]), "r"(a[1]), "r"(a[2]), "r"(a[3]), "r"(b0), "r"(b1));
}
__device__ __forceinline__ unsigned bf16x2_rn(float lo, float hi) {
    unsigned r;
    asm("cvt.rn.bf16x2.f32 %0, %1, %2;" : "=r"(r) : "f"(hi), "f"(lo));
    return r;
}
__device__ __forceinline__ void cvt_hilo(float v0, float v1, unsigned& hw, unsigned& lw) {
    hw = bf16x2_rn(v0, v1);
    float h0 = __uint_as_float(hw << 16);
    float h1 = __uint_as_float(hw & 0xFFFF0000u);
    lw = bf16x2_rn(v0 - h0, v1 - h1);
}
__device__ __forceinline__ float fast_sigmoid(float x) {
    return __fdividef(1.f, 1.f + __expf(-x));
}

// ---------------- prep (weights only) ----------------
__global__ void prep_kernel(
    const float* __restrict__ wo1,
    const float* __restrict__ w1, const float* __restrict__ g1,
    const float* __restrict__ be1, const float* __restrict__ rm1, const float* __restrict__ rv1,
    const float* __restrict__ wo2,
    const float* __restrict__ w2, const float* __restrict__ g2,
    const float* __restrict__ be2, const float* __restrict__ rm2, const float* __restrict__ rv2)
{
    int t = blockIdx.x * blockDim.x + threadIdx.x;
    int stride = gridDim.x * blockDim.x;

    for (int i = t; i < 9 * O1 * CC; i += stride) {
        int c = i & 63;
        int o = (i >> 6) & 63;
        int k = i >> 12;
        float inv = g1[o] * rsqrtf(rv1[o] + 1e-5f);
        float v = w1[(o * CC + c) * 9 + k] * inv;
        __nv_bfloat16 hb = __float2bfloat16(v);
        g_w1h[i] = hb;
        g_w1l[i] = __float2bfloat16(v - __bfloat162float(hb));
    }
    for (int i = t; i < 9 * O2 * CC; i += stride) {
        int c = i & 63;
        int o = (i >> 6) & 31;
        int k = i >> 11;
        float inv = g2[o] * rsqrtf(rv2[o] + 1e-5f);
        float v = w2[(o * CC + c) * 9 + k] * inv;
        __nv_bfloat16 hb = __float2bfloat16(v);
        g_w2h[i] = hb;
        g_w2l[i] = __float2bfloat16(v - __bfloat162float(hb));
    }
    for (int i = t; i < 9 * O2 * CC; i += stride) {
        int c = i & 63;
        int o = (i >> 6) & 31;
        int k = i >> 11;
        float v1 = (o < NOFF) ? wo1[(o * CC + c) * 9 + k] : 0.f;
        float v2 = (o < NOFF) ? wo2[(o * CC + c) * 9 + k] : 0.f;
        __nv_bfloat16 h1 = __float2bfloat16(v1);
        __nv_bfloat16 h2 = __float2bfloat16(v2);
        g_o1h[i] = h1; g_o1l[i] = __float2bfloat16(v1 - __bfloat162float(h1));
        g_o2h[i] = h2; g_o2l[i] = __float2bfloat16(v2 - __bfloat162float(h2));
    }
    if (t < O1) { float inv = g1[t] * rsqrtf(rv1[t] + 1e-5f); g_b1[t] = be1[t] - rm1[t] * inv; }
    if (t < O2) { float inv = g2[t] * rsqrtf(rv2[t] + 1e-5f); g_b2[t] = be2[t] - rm2[t] * inv; }
}

// ---------------- gathers ----------------
// bilinear tap (deform), offsets from smem soff[o][TP]
__device__ __forceinline__ void gather_bilin(
    const float* __restrict__ xc, const float* __restrict__ soff,
    int h, int p, int k,
    unsigned* hw, unsigned* lw)
{
    float dy = soff[(2 * k) * TP + p];
    float dx = soff[(2 * k + 1) * TP + p];
    float m  = soff[(18 + k) * TP + p];      // pre-sigmoided

    float ys = (float)(h + (k / 3 - 1)) + dy;
    float xs = (float)(p + (k % 3 - 1)) + dx;
    float y0f = floorf(ys), x0f = floorf(xs);
    float fy = ys - y0f, fx = xs - x0f;
    int y0 = (int)y0f, x0 = (int)x0f;
    int y1 = y0 + 1, x1 = x0 + 1;

    float vy0 = (y0 >= 0 && y0 < HH) ? m : 0.f;
    float vy1 = (y1 >= 0 && y1 < HH) ? m : 0.f;
    float vx0 = (x0 >= 0 && x0 < WW) ? 1.f : 0.f;
    float vx1 = (x1 >= 0 && x1 < WW) ? 1.f : 0.f;

    float w00 = (1.f - fy) * (1.f - fx) * vy0 * vx0;
    float w01 = (1.f - fy) * fx * vy0 * vx1;
    float w10 = fy * (1.f - fx) * vy1 * vx0;
    float w11 = fy * fx * vy1 * vx1;

    int cy0 = min(max(y0, 0), HH - 1), cy1 = min(max(y1, 0), HH - 1);
    int cx0 = min(max(x0, 0), WW - 1), cx1 = min(max(x1, 0), WW - 1);
    int i00 = cy0 * WW + cx0, i01 = cy0 * WW + cx1;
    int i10 = cy1 * WW + cx0, i11 = cy1 * WW + cx1;

#pragma unroll
    for (int j = 0; j < 16; j++) {
        const float* x0p = xc + (2 * j) * HWS;
        const float* x1p = x0p + HWS;
        float v0 = w00 * __ldg(x0p + i00) + w01 * __ldg(x0p + i01)
                 + w10 * __ldg(x0p + i10) + w11 * __ldg(x0p + i11);
        float v1 = w00 * __ldg(x1p + i00) + w01 * __ldg(x1p + i01)
                 + w10 * __ldg(x1p + i10) + w11 * __ldg(x1p + i11);
        cvt_hilo(v0, v1, hw[j], lw[j]);
    }
}

// integer row gather (offconv window): thread p loads (gy, gx=p), 32 channels
__device__ __forceinline__ void gather_row(
    const float* __restrict__ xc, int h, int p, int ky,
    unsigned* hw, unsigned* lw)
{
    int gy = h + ky - 1;
    bool ok = (gy >= 0 && gy < HH);
    const float* src = xc + gy * WW + p;
#pragma unroll
    for (int j = 0; j < 16; j++) {
        float v0 = ok ? __ldg(src + (2 * j) * HWS) : 0.f;
        float v1 = ok ? __ldg(src + (2 * j + 1) * HWS) : 0.f;
        cvt_hilo(v0, v1, hw[j], lw[j]);
    }
}

// store staged tap/row at window-row index wp
__device__ __forceinline__ void store_tap(char* sm, int wp, int cb,
                                          const unsigned* hw, const unsigned* lw)
{
#pragma unroll
    for (int j = 0; j < 8; j++) {
        unsigned boff = (unsigned)(wp * ST + cb + 4 * j) * 2u;
        *(uint2*)(sm + SM_AH + boff) = make_uint2(hw[2 * j], hw[2 * j + 1]);
        *(uint2*)(sm + SM_AL + boff) = make_uint2(lw[2 * j], lw[2 * j + 1]);
    }
}

// ---------------- phase 1: offconv via row-window staging ----------------
// A window staged once per ky (3 stagings), 3 taps served by a_base + kx*144.
__device__ __forceinline__ void run_offconv(
    char* sm, unsigned sb,
    const float* __restrict__ xc,
    const __nv_bfloat16* __restrict__ wh, const __nv_bfloat16* __restrict__ wl,
    int h, int p, int cb, int tid, int wid, int lid,
    float (&acc)[4][4])
{
    constexpr int N = 32;
    constexpr int NBI = 4;                          // (N*32)/256
    constexpr unsigned BL = SM_BH + (unsigned)N * 144u;

    const int lrow = lid & 15;
    const int lkof = (lid >> 4) * 8;
    const unsigned a_base0 = sb + ((wid * 16 + lrow) * ST + lkof) * 2;

    unsigned hw[16], lw[16];
    unsigned rbh[NBI], rbl[NBI];

    // zero boundary window rows 0 and 129 (hi and lo): 4 rows x 36 words
    for (int i = tid; i < 144; i += 256) {
        int r = i / 36, w = i % 36;
        unsigned row = (r & 1) ? 129u * STB : 0u;
        unsigned arr = (r & 2) ? SM_AL : SM_AH;
        *(unsigned*)(sm + arr + row + w * 4) = 0u;
    }

    // prologue: row 0 + B tap0
    gather_row(xc, h, p, 0, hw, lw);
    {
        const unsigned* shp = (const unsigned*)wh;
        const unsigned* slp = (const unsigned*)wl;
#pragma unroll
        for (int t2 = 0; t2 < NBI; t2++) {
            rbh[t2] = __ldg(shp + tid + t2 * 256);
            rbl[t2] = __ldg(slp + tid + t2 * 256);
        }
    }
    store_tap(sm, p + 1, cb, hw, lw);
#pragma unroll
    for (int t2 = 0; t2 < NBI; t2++) {
        int i = tid + t2 * 256;
        int n = i >> 5, kw = i & 31;
        ((unsigned*)(sm + SM_BH))[n * (ST / 2) + kw] = rbh[t2];
        ((unsigned*)(sm + BL))[n * (ST / 2) + kw] = rbl[t2];
    }
    __syncthreads();

#pragma unroll 1
    for (int t = 0; t < 9; t++) {
        const int ky = t / 3;
        const int kx = t % 3;

        // prefetch next row (at kx==2) and next B
        if (t < 8) {
            if (kx == 2)
                gather_row(xc, h, p, ky + 1, hw, lw);
            const unsigned* shp = (const unsigned*)(wh + (t + 1) * (N * CC));
            const unsigned* slp = (const unsigned*)(wl + (t + 1) * (N * CC));
#pragma unroll
            for (int t2 = 0; t2 < NBI; t2++) {
                rbh[t2] = __ldg(shp + tid + t2 * 256);
                rbl[t2] = __ldg(slp + tid + t2 * 256);
            }
        }

        // MMA tap (ky,kx): window row = pr + kx
        const unsigned a_base = a_base0 + (unsigned)kx * STB;
#pragma unroll
        for (int q = 0; q < 4; q++) {
            unsigned ah[4], al[4];
            ldsm4(ah, a_base + SM_AH + q * 32);
            ldsm4(al, a_base + SM_AL + q * 32);
#pragma unroll
            for (int nf = 0; nf < 2; nf++) {
                unsigned bh[4], bl[4];
                unsigned b_base = sb + ((nf * 16 + lrow) * ST + q * 16 + lkof) * 2;
                ldsm4(bh, b_base + SM_BH);
                ldsm4(bl, b_base + BL);
                mma16816(acc[nf * 2],     ah, bh[0], bh[2]);
                mma16816(acc[nf * 2 + 1], ah, bh[1], bh[3]);
                mma16816(acc[nf * 2],     ah, bl[0], bl[2]);
                mma16816(acc[nf * 2 + 1], ah, bl[1], bl[3]);
                mma16816(acc[nf * 2],     al, bh[0], bh[2]);
                mma16816(acc[nf * 2 + 1], al, bh[1], bh[3]);
            }
        }
        __syncthreads();

        if (t < 8) {
            if (kx == 2)
                store_tap(sm, p + 1, cb, hw, lw);
#pragma unroll
            for (int t2 = 0; t2 < NBI; t2++) {
                int i = tid + t2 * 256;
                int n = i >> 5, kw = i & 31;
                ((unsigned*)(sm + SM_BH))[n * (ST / 2) + kw] = rbh[t2];
                ((unsigned*)(sm + BL))[n * (ST / 2) + kw] = rbl[t2];
            }
            __syncthreads();
        }
    }
}

// ---------------- phase 2: deform conv, pipelined per-tap (R10 structure) ----------------
template <int N>
__device__ __forceinline__ void run_deform(
    char* sm, unsigned sb,
    const float* __restrict__ xc, const float* __restrict__ soff,
    const __nv_bfloat16* __restrict__ wh, const __nv_bfloat16* __restrict__ wl,
    int h, int p, int cb, int tid, int wid, int lid,
    float (&acc)[N / 8][4])
{
    constexpr int NF16 = N / 16;
    constexpr int NBI  = (N * 32) / 256;
    constexpr unsigned BL = SM_BH + (unsigned)N * 144u;

    const int lrow = lid & 15;
    const int lkof = (lid >> 4) * 8;
    const unsigned a_base = sb + ((wid * 16 + lrow) * ST + lkof) * 2;

    unsigned hw[16], lw[16];
    unsigned rbh[NBI], rbl[NBI];

    gather_bilin(xc, soff, h, p, 0, hw, lw);
    {
        const unsigned* shp = (const unsigned*)wh;
        const unsigned* slp = (const unsigned*)wl;
#pragma unroll
        for (int t2 = 0; t2 < NBI; t2++) {
            rbh[t2] = __ldg(shp + tid + t2 * 256);
            rbl[t2] = __ldg(slp + tid + t2 * 256);
        }
    }
    store_tap(sm, p, cb, hw, lw);
#pragma unroll
    for (int t2 = 0; t2 < NBI; t2++) {
        int i = tid + t2 * 256;
        int n = i >> 5, kw = i & 31;
        ((unsigned*)(sm + SM_BH))[n * (ST / 2) + kw] = rbh[t2];
        ((unsigned*)(sm + BL))[n * (ST / 2) + kw] = rbl[t2];
    }
    __syncthreads();

#pragma unroll 1
    for (int k = 0; k < 9; k++) {
        if (k < 8) {
            gather_bilin(xc, soff, h, p, k + 1, hw, lw);
            const unsigned* shp = (const unsigned*)(wh + (k + 1) * (N * CC));
            const unsigned* slp = (const unsigned*)(wl + (k + 1) * (N * CC));
#pragma unroll
            for (int t2 = 0; t2 < NBI; t2++) {
                rbh[t2] = __ldg(shp + tid + t2 * 256);
                rbl[t2] = __ldg(slp + tid + t2 * 256);
            }
        }

#pragma unroll
        for (int q = 0; q < 4; q++) {
            unsigned ah[4], al[4];
            ldsm4(ah, a_base + SM_AH + q * 32);
            ldsm4(al, a_base + SM_AL + q * 32);
#pragma unroll
            for (int nf = 0; nf < NF16; nf++) {
                unsigned bh[4], bl[4];
                unsigned b_base = sb + ((nf * 16 + lrow) * ST + q * 16 + lkof) * 2;
                ldsm4(bh, b_base + SM_BH);
                ldsm4(bl, b_base + BL);
                mma16816(acc[nf * 2],     ah, bh[0], bh[2]);
                mma16816(acc[nf * 2 + 1], ah, bh[1], bh[3]);
                mma16816(acc[nf * 2],     ah, bl[0], bl[2]);
                mma16816(acc[nf * 2 + 1], ah, bl[1], bl[3]);
                mma16816(acc[nf * 2],     al, bh[0], bh[2]);
                mma16816(acc[nf * 2 + 1], al, bh[1], bh[3]);
            }
        }
        __syncthreads();

        if (k < 8) {
            store_tap(sm, p, cb, hw, lw);
#pragma unroll
            for (int t2 = 0; t2 < NBI; t2++) {
                int i = tid + t2 * 256;
                int n = i >> 5, kw = i & 31;
                ((unsigned*)(sm + SM_BH))[n * (ST / 2) + kw] = rbh[t2];
                ((unsigned*)(sm + BL))[n * (ST / 2) + kw] = rbl[t2];
            }
            __syncthreads();
        }
    }
}

// ---------------- fused layer ----------------
// MODE2 1: bias+relu -> NCHW out. MODE2 2: bias+relu, gate -> out.
template <int NMAIN, int MODE2, int MINB>
__global__ __launch_bounds__(256, MINB)
void fused_layer_kernel(const float* __restrict__ xA, const float* __restrict__ xB,
                        long bstr,
                        const __nv_bfloat16* __restrict__ owh, const __nv_bfloat16* __restrict__ owl,
                        const float* __restrict__ obias,
                        const __nv_bfloat16* __restrict__ mwh, const __nv_bfloat16* __restrict__ mwl,
                        const float* __restrict__ mbias,
                        float* __restrict__ out,
                        const float* __restrict__ Aatt, const float* __restrict__ Batt)
{
    extern __shared__ __align__(16) char sm[];
    const unsigned sb = smem_u32(sm);

    constexpr unsigned SM_OFF = SM_BH + 2u * (unsigned)NMAIN * 144u;
    float* soff = (float*)(sm + SM_OFF);            // [27][128]

    const int tid = threadIdx.x;
    const int wid = tid >> 5;
    const int lid = tid & 31;

    const int b  = blockIdx.x >> 7;
    const int h  = blockIdx.x & 127;
    const int sl = h * WW;

    const int p  = tid & 127;
    const int cb = (tid >> 7) * 32;
    const float* xc = ((tid >> 7) == 0) ? (xA + b * bstr) : (xB + b * bstr);

    const int gm = lid >> 2;
    const int gn = (lid & 3) * 2;
    const int px0 = wid * 16 + gm;
    const int px1 = px0 + 8;

    // ===== phase 1: offset conv (row-window staged) =====
    {
        float acc[4][4];
#pragma unroll
        for (int i = 0; i < 4; i++)
#pragma unroll
            for (int j = 0; j < 4; j++) acc[i][j] = 0.f;

        run_offconv(sm, sb, xc, owh, owl, h, p, cb, tid, wid, lid, acc);

#pragma unroll
        for (int nf = 0; nf < 4; nf++) {
            int o = nf * 8 + gn;
#pragma unroll
            for (int e = 0; e < 2; e++) {
                int oo = o + e;
                if (oo < NOFF) {
                    float bb = __ldg(obias + oo);
                    float v0 = acc[nf][e] + bb;
                    float v1 = acc[nf][e + 2] + bb;
                    if (oo >= 18) {
                        v0 = fast_sigmoid(v0);
                        v1 = fast_sigmoid(v1);
                    }
                    soff[oo * TP + px0] = v0;
                    soff[oo * TP + px1] = v1;
                }
            }
        }
        __syncthreads();
    }

    // ===== phase 2: deform conv =====
    {
        float acc[NMAIN / 8][4];
#pragma unroll
        for (int i = 0; i < NMAIN / 8; i++)
#pragma unroll
            for (int j = 0; j < 4; j++) acc[i][j] = 0.f;

        run_deform<NMAIN>(sm, sb, xc, soff, mwh, mwl, h, p, cb, tid, wid, lid, acc);

        const int g0 = sl + px0;
        const int g1i = sl + px1;

        float ga0 = 1.f, ga1 = 1.f;
        if (MODE2 == 2) {
            ga0 = (1.f - __ldg(Aatt + b * HWS + g0)) * __ldg(Batt + b * HWS + g0);
            ga1 = (1.f - __ldg(Aatt + b * HWS + g1i)) * __ldg(Batt + b * HWS + g1i);
        }

#pragma unroll
        for (int nf = 0; nf < NMAIN / 8; nf++) {
            int o = nf * 8 + gn;
#pragma unroll
            for (int e = 0; e < 2; e++) {
                int oo = o + e;
                float bb = __ldg(mbias + oo);
                float v0 = fmaxf(acc[nf][e] + bb, 0.f);
                float v1 = fmaxf(acc[nf][e + 2] + bb, 0.f);
                if (MODE2 == 2) { v0 *= ga0; v1 *= ga1; }
                out[(b * NMAIN + oo) * HWS + g0]  = v0;
                out[(b * NMAIN + oo) * HWS + g1i] = v1;
            }
        }
    }
}

// ---------------- launch ----------------
extern "C" void kernel_launch(void* const* d_in, const int* in_sizes, int n_in,
                              void* d_out, int out_size)
{
    const float* pA   = (const float*)d_in[1];
    const float* pB   = (const float*)d_in[2];
    const float* Aatt = (const float*)d_in[3];
    const float* Batt = (const float*)d_in[4];
    const float* wo1  = (const float*)d_in[5];
    const float* bo1  = (const float*)d_in[6];
    const float* w1   = (const float*)d_in[7];
    const float* g1   = (const float*)d_in[8];
    const float* be1  = (const float*)d_in[9];
    const float* rm1  = (const float*)d_in[10];
    const float* rv1  = (const float*)d_in[11];
    const float* wo2  = (const float*)d_in[12];
    const float* bo2  = (const float*)d_in[13];
    const float* w2   = (const float*)d_in[14];
    const float* g2   = (const float*)d_in[15];
    const float* be2  = (const float*)d_in[16];
    const float* rm2  = (const float*)d_in[17];
    const float* rv2  = (const float*)d_in[18];

    float *x2, *pb1, *pb2;
    __nv_bfloat16 *w1h, *w1l, *w2h, *w2l, *o1h, *o1l, *o2h, *o2l;
    cudaGetSymbolAddress((void**)&x2,  g_x2);
    cudaGetSymbolAddress((void**)&pb1, g_b1);
    cudaGetSymbolAddress((void**)&pb2, g_b2);
    cudaGetSymbolAddress((void**)&w1h, g_w1h);
    cudaGetSymbolAddress((void**)&w1l, g_w1l);
    cudaGetSymbolAddress((void**)&w2h, g_w2h);
    cudaGetSymbolAddress((void**)&w2l, g_w2l);
    cudaGetSymbolAddress((void**)&o1h, g_o1h);
    cudaGetSymbolAddress((void**)&o1l, g_o1l);
    cudaGetSymbolAddress((void**)&o2h, g_o2h);
    cudaGetSymbolAddress((void**)&o2l, g_o2l);

    const int smem1 = SM_BH + 2 * (O1 * 144) + NOFF * TP * 4;   // 69696
    const int smem2 = SM_BH + 2 * (O2 * 144) + NOFF * TP * 4;   // 60480
    cudaFuncSetAttribute(fused_layer_kernel<O1, 1, 2>, cudaFuncAttributeMaxDynamicSharedMemorySize, smem1);
    cudaFuncSetAttribute(fused_layer_kernel<O2, 2, 3>, cudaFuncAttributeMaxDynamicSharedMemorySize, smem2);

    dim3 blk(256);
    dim3 grd(NPIX / TP);   // 512

    prep_kernel<<<64, 256>>>(wo1, w1, g1, be1, rm1, rv1,
                             wo2, w2, g2, be2, rm2, rv2);

    fused_layer_kernel<O1, 1, 2><<<grd, blk, smem1>>>(
        pB, pA, 32L * HWS, o1h, o1l, bo1, w1h, w1l, pb1, x2, nullptr, nullptr);
    fused_layer_kernel<O2, 2, 3><<<grd, blk, smem2>>>(
        x2, x2 + 32 * HWS, 64L * HWS, o2h, o2l, bo2, w2h, w2l, pb2,
        (float*)d_out, Aatt, Batt);
}